// round 14
// baseline (speedup 1.0000x reference)
#include <cuda_runtime.h>
#include <cuda_fp16.h>
#include <math.h>
#include <stdint.h>

#define BATCH 4

__device__ __half g_h1h[67108864];   // conv1 out, pixel-major fp16 hi [ub][HW][64]
__device__ __half g_h1l[67108864];   // fp16 lo residual
__device__ float  g_h2 [33554432];   // conv2 out fp32 planar [ub][32][HW]
__device__ float  g_msf[BATCH * 512 * 512];

// ---------------- warp-MMA helpers (plain sm_103-safe PTX) ----------------
__device__ __forceinline__ uint32_t smem_u32(const void* p) {
    uint32_t a;
    asm("{ .reg .u64 t; cvta.to.shared.u64 t, %1; cvt.u32.u64 %0, t; }" : "=r"(a) : "l"(p));
    return a;
}
__device__ __forceinline__ void ldmat4(uint32_t* a, uint32_t addr) {
    asm volatile("ldmatrix.sync.aligned.m8n8.x4.shared.b16 {%0,%1,%2,%3}, [%4];"
        : "=r"(a[0]), "=r"(a[1]), "=r"(a[2]), "=r"(a[3]) : "r"(addr));
}
__device__ __forceinline__ void mma16816(float* c, const uint32_t* a,
                                         uint32_t b0, uint32_t b1) {
    asm volatile("mma.sync.aligned.m16n8k16.row.col.f32.f16.f16.f32 "
        "{%0,%1,%2,%3}, {%4,%5,%6,%7}, {%8,%9}, {%0,%1,%2,%3};"
        : "+f"(c[0]), "+f"(c[1]), "+f"(c[2]), "+f"(c[3])
        : "r"(a[0]), "r"(a[1]), "r"(a[2]), "r"(a[3]), "r"(b0), "r"(b1));
}

// conv2 SMEM layout (bytes). Pixel pitch 144 (conflict-free ldmatrix).
#define SLOT_B   9792            // 68 px * 144
#define A_HI     0
#define A_LO     58752           // 6 slots * 9792
#define B_OFF    117504
#define C2_SMEM  219904          // + 400 frags * 256B

// conv1 SMEM layout (bytes)
#define A1_PITCH 208             // 96 k halfs + 8 pad (13 x 16B chunks: conflict-free)
#define A1_HI    0               // 128 rows * 208 = 26624
#define A1_LO    26624
#define B1_OFF   53248           // 96 frags * 256 = 24576
#define ST_OFF   77824           // 10 rows * 136 cols * 4B = 5440
#define BIAS_OFF 83264           // 256
#define C1_SMEM  83520

// ---------------------------------------------------------------------------
// conv1 tensor-core: 1->64, 9x9, pad 4, ReLU. im2col GEMM M=128 N=64 K=96.
// Writes pixel-major hi/lo fp16 directly (h1_split eliminated).
// ---------------------------------------------------------------------------
__global__ __launch_bounds__(256, 1) void conv1_tc_kernel(
    const float* __restrict__ in, int use_msf,
    const float* __restrict__ Wp, const float* __restrict__ Bp,
    int H, int W)
{
    extern __shared__ __align__(16) char smem[];
    uint32_t sb = smem_u32(smem);
    int tid = threadIdx.x, wid = tid >> 5, lane = tid & 31;
    int ub = blockIdx.z, u = ub / BATCH, b = ub % BATCH;
    int P0 = blockIdx.x * 128;
    int HW = H * W;
    const float* src = (use_msf ? g_msf : in) + (size_t)b * HW;
    int y0 = P0 / W;
    int x0 = P0 - y0 * W;
    int wide = (W >= 128);

    if (tid < 64) ((float*)(smem + BIAS_OFF))[tid] = Bp[u * 64 + tid];

    // --- B fragments: f = ks*16 + n8*2 + prod ---
    const float* wu = Wp + (size_t)u * 64 * 81;
    for (int j = tid; j < 96 * 32; j += 256) {
        int t = j & 31, f = j >> 5;
        int prod = f & 1, n8 = (f >> 1) & 7, ks = f >> 4;
        int oc = n8 * 8 + (t >> 2);
        int k0 = ks * 16 + (t & 3) * 2;
        float w0 = (k0     < 81) ? wu[oc * 81 + k0]     : 0.f;
        float w1 = (k0 + 1 < 81) ? wu[oc * 81 + k0 + 1] : 0.f;
        float w2 = (k0 + 8 < 81) ? wu[oc * 81 + k0 + 8] : 0.f;
        float w3 = (k0 + 9 < 81) ? wu[oc * 81 + k0 + 9] : 0.f;
        __half h0 = __float2half_rn(w0), h1 = __float2half_rn(w1);
        __half h2 = __float2half_rn(w2), h3 = __float2half_rn(w3);
        if (prod) {
            h0 = __float2half_rn(w0 - __half2float(h0));
            h1 = __float2half_rn(w1 - __half2float(h1));
            h2 = __float2half_rn(w2 - __half2float(h2));
            h3 = __float2half_rn(w3 - __half2float(h3));
        }
        __half hp[4] = { h0, h1, h2, h3 };
        *(uint2*)(smem + B1_OFF + f * 256 + t * 8) = *(uint2*)hp;
    }

    // --- stage input rows (zero-clamped) ---
    int nrows = wide ? 9 : 10;
    int ncols = wide ? 136 : 72;
    int xbase = wide ? x0 - 4 : -4;
    int ybase = y0 - 4;
    float* st = (float*)(smem + ST_OFF);
    for (int j = tid; j < nrows * ncols; j += 256) {
        int r = j / ncols, c = j - r * ncols;
        int gy = ybase + r, gx = xbase + c;
        st[r * 136 + c] = (gy >= 0 && gy < H && gx >= 0 && gx < W)
                        ? src[(size_t)gy * W + gx] : 0.f;
    }
    __syncthreads();

    // --- im2col A build: thread t -> pixel i = t>>1, k-half = (t&1)*48 ---
    {
        int i = tid >> 1;
        int kb = (tid & 1) * 48;
        int p = P0 + i;
        int yy = p / W;
        int xx = p - yy * W;
        int srow0 = yy - y0;
        int scb = wide ? i : xx;
        __half* ah = (__half*)(smem + A1_HI + i * A1_PITCH);
        __half* al = (__half*)(smem + A1_LO + i * A1_PITCH);
#pragma unroll
        for (int j = 0; j < 48; j++) {
            int k = kb + j;
            float v = 0.f;
            if (k < 81) {
                int ky = (k * 57) >> 9;     // k/9 for k<96
                int kx = k - ky * 9;
                v = st[(srow0 + ky) * 136 + scb + kx];
            }
            __half h = __float2half_rn(v);
            ah[k] = h;
            al[k] = __float2half_rn(v - __half2float(h));
        }
    }
    __syncthreads();

    // --- mainloop: warp wid owns m16 tile i0 = wid*16 ---
    float c[8][4];
#pragma unroll
    for (int n8 = 0; n8 < 8; n8++)
#pragma unroll
        for (int i = 0; i < 4; i++) c[n8][i] = 0.f;

    uint32_t abase_h = sb + A1_HI
        + (uint32_t)(wid * 16 + (lane & 15)) * A1_PITCH + (lane >> 4) * 16;
    uint32_t abase_l = abase_h + (A1_LO - A1_HI);
#pragma unroll
    for (int ks = 0; ks < 6; ks++) {
        uint32_t ah[4], al[4];
        ldmat4(ah, abase_h + ks * 32);
        ldmat4(al, abase_l + ks * 32);
        uint32_t fb = sb + B1_OFF + (uint32_t)ks * 16 * 256 + lane * 8;
#pragma unroll
        for (int n8 = 0; n8 < 8; n8++) {
            uint32_t fo = fb + (uint32_t)n8 * 2 * 256;
            uint32_t bh0, bh1, bl0, bl1;
            asm volatile("ld.shared.v2.b32 {%0,%1}, [%2];" : "=r"(bh0), "=r"(bh1) : "r"(fo));
            asm volatile("ld.shared.v2.b32 {%0,%1}, [%2];" : "=r"(bl0), "=r"(bl1) : "r"(fo + 256));
            mma16816(c[n8], ah, bh0, bh1);
            mma16816(c[n8], ah, bl0, bl1);
            mma16816(c[n8], al, bh0, bh1);
        }
    }

    // --- epilogue: ReLU, hi/lo split, pixel-major stores ---
    const float* bias = (const float*)(smem + BIAS_OFF);
    int pxa = P0 + wid * 16 + (lane >> 2);
    int oc2 = (lane & 3) * 2;
    __half* dh = g_h1h + (size_t)ub * HW * 64;
    __half* dl = g_h1l + (size_t)ub * HW * 64;
#pragma unroll
    for (int n8 = 0; n8 < 8; n8++) {
        int ocn = n8 * 8 + oc2;
        float b0 = bias[ocn], b1 = bias[ocn + 1];
        float v00 = fmaxf(c[n8][0] + b0, 0.f), v01 = fmaxf(c[n8][1] + b1, 0.f);
        float v10 = fmaxf(c[n8][2] + b0, 0.f), v11 = fmaxf(c[n8][3] + b1, 0.f);
        __half h00 = __float2half_rn(v00), h01 = __float2half_rn(v01);
        __half h10 = __float2half_rn(v10), h11 = __float2half_rn(v11);
        __half l00 = __float2half_rn(v00 - __half2float(h00));
        __half l01 = __float2half_rn(v01 - __half2float(h01));
        __half l10 = __float2half_rn(v10 - __half2float(h10));
        __half l11 = __float2half_rn(v11 - __half2float(h11));
        __half p0[2] = { h00, h01 }, p1[2] = { h10, h11 };
        __half q0[2] = { l00, l01 }, q1[2] = { l10, l11 };
        *(uint32_t*)(dh + (size_t)pxa * 64 + ocn)       = *(uint32_t*)p0;
        *(uint32_t*)(dh + (size_t)(pxa + 8) * 64 + ocn) = *(uint32_t*)p1;
        *(uint32_t*)(dl + (size_t)pxa * 64 + ocn)       = *(uint32_t*)q0;
        *(uint32_t*)(dl + (size_t)(pxa + 8) * 64 + ocn) = *(uint32_t*)q1;
    }
}

// ---------------------------------------------------------------------------
// conv2 tensor-core (mma.sync): 64->32, 5x5, pad 2, ReLU. (R10 version,
// planar fp32 output.)
// ---------------------------------------------------------------------------
__global__ __launch_bounds__(256, 1) void conv2_tc_kernel(
    const float* __restrict__ Wp, const float* __restrict__ Bp,
    int H, int W)
{
    extern __shared__ __align__(16) char smem[];
    uint32_t sb = smem_u32(smem);
    int tid = threadIdx.x, wid = tid >> 5, lane = tid & 31;
    int zz = blockIdx.z;
    int ocg = zz & 1, ub = zz >> 1, u = ub / BATCH;
    int oc0 = ocg * 16;
    int x0 = blockIdx.x * 64;
    int HW = H * W;
    int S = H >> 3;                    // rows per CTA (gridDim.y == 8)
    int ybase = blockIdx.y * S, yend = ybase + S;

    const float* wub = Wp + (size_t)u * 32 * 1600;
    for (int j = tid; j < 12800; j += 256) {
        int t = j & 31, f = j >> 5;
        int prod = f & 1, n8 = (f >> 1) & 1, k = (f >> 2) & 3, tap = f >> 4;
        int col = t >> 2, icb = k * 16 + (t & 3) * 2;
        int oc = oc0 + n8 * 8 + col;
        const float* wp = wub + (size_t)(oc) * 1600 + tap;
        float w0 = wp[(icb + 0) * 25], w1 = wp[(icb + 1) * 25];
        float w2 = wp[(icb + 8) * 25], w3 = wp[(icb + 9) * 25];
        __half h0 = __float2half_rn(w0), h1 = __float2half_rn(w1);
        __half h2 = __float2half_rn(w2), h3 = __float2half_rn(w3);
        if (prod) {
            h0 = __float2half_rn(w0 - __half2float(h0));
            h1 = __float2half_rn(w1 - __half2float(h1));
            h2 = __float2half_rn(w2 - __half2float(h2));
            h3 = __float2half_rn(w3 - __half2float(h3));
        }
        __half hp[4] = { h0, h1, h2, h3 };
        *(uint2*)(smem + B_OFF + f * 256 + t * 8) = *(uint2*)hp;
    }

    const __half* h1h = g_h1h + (size_t)ub * HW * 64;
    const __half* h1l = g_h1l + (size_t)ub * HW * 64;

    auto stage = [&](int r0, int nrows) {
        int total = nrows * 2 * 68 * 8;
        for (int j = tid; j < total; j += 256) {
            int ic4 = j & 7;
            int t2 = j >> 3;
            int px = t2 % 68;
            int pl = t2 / 68;
            int row = pl >> 1, half = pl & 1;
            int r = r0 + row;
            int x = x0 - 2 + px;
            uint4 v = make_uint4(0, 0, 0, 0);
            if (r >= 0 && r < H && x >= 0 && x < W) {
                const __half* s = half ? h1l : h1h;
                v = *(const uint4*)(s + ((size_t)r * W + x) * 64 + ic4 * 8);
            }
            uint32_t off = (half ? A_LO : A_HI)
                         + (uint32_t)(((r + 6) % 6)) * SLOT_B + px * 144 + ic4 * 16;
            *(uint4*)(smem + off) = v;
        }
    };

    stage(ybase - 2, 6);
    __syncthreads();

    int ygrp = wid >> 2, wx = wid & 3;
    int lane15 = lane & 15, kadd = (lane >> 4) * 16;

    for (int y = ybase; y < yend; y += 2) {
        int y_out = y + ygrp;
        float c[2][3][4];
#pragma unroll
        for (int n8 = 0; n8 < 2; n8++)
#pragma unroll
            for (int p = 0; p < 3; p++)
#pragma unroll
                for (int i = 0; i < 4; i++) c[n8][p][i] = 0.f;

        for (int dy = 0; dy < 5; dy++) {
            int ra = y_out + dy - 2;
            uint32_t rbH = sb + A_HI + (uint32_t)((ra + 6) % 6) * SLOT_B;
            uint32_t rbL = rbH + A_LO;
            for (int dx = 0; dx < 5; dx++) {
                uint32_t arow = (uint32_t)(wx * 16 + dx + lane15) * 144 + kadd;
                uint32_t fbase = sb + B_OFF + (uint32_t)(dy * 5 + dx) * 16 * 256 + lane * 8;
#pragma unroll
                for (int k = 0; k < 4; k++) {
                    uint32_t ah[4], al[4];
                    ldmat4(ah, rbH + arow + k * 32);
                    ldmat4(al, rbL + arow + k * 32);
#pragma unroll
                    for (int n8 = 0; n8 < 2; n8++) {
                        uint32_t fo = fbase + (uint32_t)(k * 4 + n8 * 2) * 256;
                        uint32_t bh0, bh1, bl0, bl1;
                        asm volatile("ld.shared.v2.b32 {%0,%1}, [%2];"
                                     : "=r"(bh0), "=r"(bh1) : "r"(fo));
                        asm volatile("ld.shared.v2.b32 {%0,%1}, [%2];"
                                     : "=r"(bl0), "=r"(bl1) : "r"(fo + 256));
                        mma16816(c[n8][0], ah, bh0, bh1);
                        mma16816(c[n8][1], ah, bl0, bl1);
                        mma16816(c[n8][2], al, bh0, bh1);
                    }
                }
            }
        }

        int px = lane >> 2, colp = (lane & 3) * 2;
#pragma unroll
        for (int n8 = 0; n8 < 2; n8++) {
            int ocl = oc0 + n8 * 8 + colp;
            float b0v = __ldg(Bp + u * 32 + ocl);
            float b1v = __ldg(Bp + u * 32 + ocl + 1);
            float s0 = c[n8][0][0] + c[n8][1][0] + c[n8][2][0] + b0v;
            float s1 = c[n8][0][1] + c[n8][1][1] + c[n8][2][1] + b1v;
            float s2 = c[n8][0][2] + c[n8][1][2] + c[n8][2][2] + b0v;
            float s3 = c[n8][0][3] + c[n8][1][3] + c[n8][2][3] + b1v;
            float* base = g_h2 + ((size_t)ub * 32 + ocl) * HW
                        + (size_t)y_out * W + x0 + wx * 16;
            base[px]          = fmaxf(s0, 0.f);
            base[HW + px]     = fmaxf(s1, 0.f);
            base[px + 8]      = fmaxf(s2, 0.f);
            base[HW + px + 8] = fmaxf(s3, 0.f);
        }
        __syncthreads();
        if (y + 2 < yend) {
            stage(y + 4, 2);
            __syncthreads();
        }
    }
}

// ---------------------------------------------------------------------------
// conv3: 32 -> 1, 5x5, pad 2, no ReLU (R10 shared-tile version).
// ---------------------------------------------------------------------------
__global__ __launch_bounds__(256) void conv3_kernel(
    const float* __restrict__ Wp, const float* __restrict__ Bp,
    float* __restrict__ outsec, int H, int W, int interleave)
{
    __shared__ float s_in[36][36];
    __shared__ float s_w[25];

    int z = blockIdx.z;
    int u = z / BATCH, b = z % BATCH;
    int tid = threadIdx.y * 16 + threadIdx.x;

    const float* wbase = Wp + (size_t)u * 32 * 25;
    float bv = Bp[u];
    float a00 = bv, a01 = bv, a10 = bv, a11 = bv;

    int ty0 = blockIdx.y * 32 - 2, tx0 = blockIdx.x * 32 - 2;
    const float* h2b = g_h2 + ((size_t)z * 32) * H * W;
    int iy = threadIdx.y * 2, ix = threadIdx.x * 2;

    for (int ic = 0; ic < 32; ic++) {
        __syncthreads();
        const float* inc = h2b + (size_t)ic * H * W;
        for (int i = tid; i < 36 * 36; i += 256) {
            int r = i / 36, c = i % 36;
            int gy = ty0 + r, gx = tx0 + c;
            s_in[r][c] = (gy >= 0 && gy < H && gx >= 0 && gx < W) ? inc[gy * W + gx] : 0.f;
        }
        if (tid < 25) s_w[tid] = wbase[ic * 25 + tid];
        __syncthreads();

#pragma unroll
        for (int ky = 0; ky < 5; ky++) {
            float rA[6], rB[6];
#pragma unroll
            for (int j = 0; j < 6; j++) {
                rA[j] = s_in[iy + ky][ix + j];
                rB[j] = s_in[iy + ky + 1][ix + j];
            }
#pragma unroll
            for (int kx = 0; kx < 5; kx++) {
                float w = s_w[ky * 5 + kx];
                a00 = fmaf(rA[kx],     w, a00);
                a01 = fmaf(rA[kx + 1], w, a01);
                a10 = fmaf(rB[kx],     w, a10);
                a11 = fmaf(rB[kx + 1], w, a11);
            }
        }
    }

    int oy = blockIdx.y * 32 + iy, ox = blockIdx.x * 32 + ix;
    int s  = interleave ? 2 : 1;
    int ry = interleave ? (u >> 1) : 0;
    int rx = interleave ? (u & 1) : 0;
    int OW = s * W, OH = s * H;
    float* ob = outsec + (size_t)b * OH * OW;
    ob[(size_t)(s * oy + ry)       * OW + s * ox       + rx] = a00;
    ob[(size_t)(s * oy + ry)       * OW + s * (ox + 1) + rx] = a01;
    ob[(size_t)(s * (oy + 1) + ry) * OW + s * ox       + rx] = a10;
    ob[(size_t)(s * (oy + 1) + ry) * OW + s * (ox + 1) + rx] = a11;
}

// ---------------------------------------------------------------------------
__device__ __forceinline__ float bil_up(const float* img, int N, int sc, int y, int x)
{
    float fy = (y + 0.5f) / sc - 0.5f;
    float fx = (x + 0.5f) / sc - 0.5f;
    int y0 = (int)floorf(fy); float wy = fy - y0;
    int x0 = (int)floorf(fx); float wx = fx - x0;
    int y0c = y0 < 0 ? 0 : y0;  int y1c = y0 + 1 > N - 1 ? N - 1 : y0 + 1;
    int x0c = x0 < 0 ? 0 : x0;  int x1c = x0 + 1 > N - 1 ? N - 1 : x0 + 1;
    float p00 = img[(size_t)y0c * N + x0c], p01 = img[(size_t)y0c * N + x1c];
    float p10 = img[(size_t)y1c * N + x0c], p11 = img[(size_t)y1c * N + x1c];
    return (1.f - wy) * ((1.f - wx) * p00 + wx * p01)
         +        wy  * ((1.f - wx) * p10 + wx * p11);
}

__global__ __launch_bounds__(256) void msf_in_kernel(const float* __restrict__ outbuf)
{
    int idx = blockIdx.x * blockDim.x + threadIdx.x;
    if (idx >= BATCH * 512 * 512) return;
    int x = idx & 511;
    int y = (idx >> 9) & 511;
    int b = idx >> 18;
    const float* x2 = outbuf + 0      + (size_t)b * 128 * 128;
    const float* x4 = outbuf + 65536  + (size_t)b * 256 * 256;
    const float* x8 = outbuf + 327680 + (size_t)b * 512 * 512;
    g_msf[idx] = bil_up(x2, 128, 4, y, x)
               + bil_up(x4, 256, 2, y, x)
               + x8[(size_t)y * 512 + x];
}

// ---------------------------------------------------------------------------
extern "C" void kernel_launch(void* const* d_in, const int* in_sizes, int n_in,
                              void* d_out, int out_size)
{
    const float* image = (const float*)d_in[0];
    const float* W1 = (const float*)d_in[1];
    const float* B1 = (const float*)d_in[2];
    const float* W2 = (const float*)d_in[3];
    const float* B2 = (const float*)d_in[4];
    const float* W3 = (const float*)d_in[5];
    const float* B3 = (const float*)d_in[6];
    float* out = (float*)d_out;

    static int smem_set = 0;
    if (!smem_set) {
        cudaFuncSetAttribute(conv2_tc_kernel,
                             cudaFuncAttributeMaxDynamicSharedMemorySize, C2_SMEM);
        cudaFuncSetAttribute(conv1_tc_kernel,
                             cudaFuncAttributeMaxDynamicSharedMemorySize, C1_SMEM);
        smem_set = 1;
    }

    float* sec_x2  = out;
    float* sec_x4  = out + 65536;
    float* sec_x8  = out + 327680;
    float* sec_msf = out + 1376256;

    struct Stage { const float* in; int use_msf, H, W, ub, U, inter; float* osec; };
    Stage st[4] = {
        { image,   0,  64,  64,  0, 4, 1, sec_x2  },
        { sec_x2,  0, 128, 128,  4, 4, 1, sec_x4  },
        { sec_x4,  0, 256, 256,  8, 4, 1, sec_x8  },
        { nullptr, 1, 512, 512, 12, 1, 0, sec_msf },
    };

    dim3 blk(16, 16);
    for (int s = 0; s < 4; s++) {
        if (s == 3)
            msf_in_kernel<<<(BATCH * 512 * 512 + 255) / 256, 256>>>(out);
        Stage& t = st[s];
        int UB = t.U * BATCH, HW = t.H * t.W;
        conv1_tc_kernel<<<dim3(HW / 128, 1, UB), 256, C1_SMEM>>>(
            t.in, t.use_msf,
            W1 + (size_t)t.ub * 64 * 81, B1 + (size_t)t.ub * 64, t.H, t.W);
        conv2_tc_kernel<<<dim3(t.W / 64, 8, UB * 2), 256, C2_SMEM>>>(
            W2 + (size_t)t.ub * 32 * 64 * 25, B2 + (size_t)t.ub * 32, t.H, t.W);
        conv3_kernel<<<dim3(t.W / 32, t.H / 32, UB), blk>>>(
            W3 + (size_t)t.ub * 32 * 25, B3 + t.ub, t.osec, t.H, t.W, t.inter);
    }
}